// round 16
// baseline (speedup 1.0000x reference)
#include <cuda_runtime.h>
#include <cuda_bf16.h>
#include <cuda_fp16.h>
#include <cuda_fp8.h>
#include <math.h>
#include <cstdint>

constexpr int Bn = 4096;
constexpr int D  = 1024;
constexpr int NR = 8192;
constexpr float INV_T = 1.0f / 0.07f;
constexpr float FP8_SCALE = 16.0f;                       // features stored as e4m3(16*f)
constexpr float EXP2S = 1.4426950408889634f / (0.07f * 256.0f);

constexpr int BM = 128, BN = 128;
constexpr int BKB = 128;                  // fp8 K elems per stage (full 128-B row)
constexpr int KITERS = D / BKB;           // 8
constexpr int NSTAGE = 3;
constexpr int TILE_BYTES  = 128 * 128;    // 16384
constexpr int STAGE_BYTES = 2 * TILE_BYTES;
constexpr int SMEM_DYN = NSTAGE * STAGE_BYTES + 512 + 16;
constexpr int NT = NR / BM;               // 64
constexpr int NTRI = NT * (NT + 1) / 2;   // 2080

__device__ uint8_t g_F8[(size_t)NR * D];
__device__ float g_rowsum[NR];
__device__ float g_posvec[Bn];

// ---------------- helpers ----------------
__device__ __forceinline__ uint32_t smem_u32(const void* p) {
    uint32_t a;
    asm("{ .reg .u64 t; cvta.to.shared.u64 t, %1; cvt.u32.u64 %0, t; }" : "=r"(a) : "l"(p));
    return a;
}
__device__ __forceinline__ void cp16(uint32_t dst, const void* src) {
    asm volatile("cp.async.cg.shared.global [%0], [%1], 16;" :: "r"(dst), "l"(src) : "memory");
}
__device__ __forceinline__ void ldmx4(uint32_t* r, uint32_t addr) {
    asm volatile("ldmatrix.sync.aligned.m8n8.x4.shared.b16 {%0,%1,%2,%3}, [%4];"
                 : "=r"(r[0]), "=r"(r[1]), "=r"(r[2]), "=r"(r[3]) : "r"(addr));
}
// fp8 mma with f16 accumulators
__device__ __forceinline__ void mma_fp8h(uint32_t* c, const uint32_t* a, uint32_t b0, uint32_t b1) {
    asm volatile("mma.sync.aligned.m16n8k32.row.col.f16.e4m3.e4m3.f16 "
                 "{%0,%1}, {%2,%3,%4,%5}, {%6,%7}, {%0,%1};"
                 : "+r"(c[0]), "+r"(c[1])
                 : "r"(a[0]), "r"(a[1]), "r"(a[2]), "r"(a[3]), "r"(b0), "r"(b1));
}
__device__ __forceinline__ float ex2(float x) {
    float r;
    asm("ex2.approx.ftz.f32 %0, %1;" : "=f"(r) : "f"(x));
    return r;
}
__device__ __forceinline__ float warpReduceSum(float v) {
#pragma unroll
    for (int o = 16; o > 0; o >>= 1) v += __shfl_xor_sync(0xffffffffu, v, o);
    return v;
}
__device__ __forceinline__ float blockReduceSum(float v) {
    __shared__ float sh[32];
    int lane = threadIdx.x & 31, wid = threadIdx.x >> 5;
    v = warpReduceSum(v);
    if (lane == 0) sh[wid] = v;
    __syncthreads();
    int nw = blockDim.x >> 5;
    v = (threadIdx.x < nw) ? sh[lane] : 0.0f;
    if (wid == 0) v = warpReduceSum(v);
    return v;
}

// ---------------- prep: warp per pair, TWO-PASS (low regs, high occupancy) ----------------
// Pass 1 streams norms/dot (nothing held live); pass 2 reloads (L2-hot) and quantizes.
__global__ void __launch_bounds__(256) k_prep(const float* __restrict__ f1,
                                              const float* __restrict__ f2) {
    const int wid = threadIdx.x >> 5, lane = threadIdx.x & 31;
    const int i = blockIdx.x * 8 + wid;          // pair index
    const float* p1 = &f1[(size_t)i * D + lane * 4];
    const float* p2 = &f2[(size_t)i * D + lane * 4];

    float ss1 = 0.0f, ss2 = 0.0f, dd = 0.0f;
#pragma unroll
    for (int j = 0; j < 8; j++) {
        float4 a = *(const float4*)(p1 + j * 128);
        float4 b = *(const float4*)(p2 + j * 128);
        ss1 += a.x * a.x + a.y * a.y + a.z * a.z + a.w * a.w;
        ss2 += b.x * b.x + b.y * b.y + b.z * b.z + b.w * b.w;
        dd  += a.x * b.x + a.y * b.y + a.z * b.z + a.w * b.w;
    }
    ss1 = warpReduceSum(ss1);
    ss2 = warpReduceSum(ss2);
    dd  = warpReduceSum(dd);
    const float n1 = fmaxf(sqrtf(ss1), 1e-12f), n2 = fmaxf(sqrtf(ss2), 1e-12f);
    const float i1 = FP8_SCALE / n1, i2 = FP8_SCALE / n2;
    if (lane == 0) {
        g_posvec[i] = dd / (n1 * n2) * INV_T;
        g_rowsum[i] = 0.0f;
        g_rowsum[i + Bn] = 0.0f;
    }

    uint8_t* q1 = &g_F8[(size_t)i * D + lane * 4];
    uint8_t* q2 = &g_F8[(size_t)(i + Bn) * D + lane * 4];
#pragma unroll
    for (int j = 0; j < 8; j++) {
        float4 a = *(const float4*)(p1 + j * 128);
        __nv_fp8_e4m3 a0(a.x * i1), a1(a.y * i1), a2(a.z * i1), a3(a.w * i1);
        *(uchar4*)(q1 + j * 128) =
            make_uchar4(*(uint8_t*)&a0, *(uint8_t*)&a1, *(uint8_t*)&a2, *(uint8_t*)&a3);
        float4 b = *(const float4*)(p2 + j * 128);
        __nv_fp8_e4m3 b0(b.x * i2), b1(b.y * i2), b2(b.z * i2), b3(b.w * i2);
        *(uchar4*)(q2 + j * 128) =
            make_uchar4(*(uint8_t*)&b0, *(uint8_t*)&b1, *(uint8_t*)&b2, *(uint8_t*)&b3);
    }
}

// ---------------- final reduction (separate kernel — keeps k_gemm regs low) ----------------
__global__ void k_final(float* __restrict__ out) {
    float4 v0 = *(const float4*)&g_rowsum[threadIdx.x * 8];
    float4 v1 = *(const float4*)&g_rowsum[threadIdx.x * 8 + 4];
    float s = __logf(v0.x) + __logf(v0.y) + __logf(v0.z) + __logf(v0.w)
            + __logf(v1.x) + __logf(v1.y) + __logf(v1.z) + __logf(v1.w);
    float4 p4 = *(const float4*)&g_posvec[threadIdx.x * 4];
    float p = p4.x + p4.y + p4.z + p4.w;
    s = blockReduceSum(s);
    __syncthreads();
    p = blockReduceSum(p);
    if (threadIdx.x == 0) out[0] = s / (float)NR - p / (float)Bn;
}

// ---------------- main GEMM (upper triangle) + exp/rowsum ----------------
__global__ void __launch_bounds__(256, 2) k_gemm() {
    const int t = blockIdx.x;
    int I = (int)(64.5f - sqrtf(64.5f * 64.5f - 2.0f * (float)t));
    while (NT * I - I * (I - 1) / 2 > t) I--;
    while (NT * (I + 1) - (I + 1) * I / 2 <= t) I++;
    const int J = I + (t - (NT * I - I * (I - 1) / 2));
    const bool diag = (I == J);
    const int m0 = I * BM, n0 = J * BN;

    extern __shared__ char smem_raw[];
    const uint32_t base = smem_u32(smem_raw);
    float* cs = (float*)(smem_raw + NSTAGE * STAGE_BYTES);

    const int tid = threadIdx.x, lane = tid & 31, wid = tid >> 5;
    const int wm = wid & 3, wn = wid >> 2;           // 4 x 2 warp grid, 32x64 warp tiles

    if (tid < 128) cs[tid] = 0.0f;

    // stage loader: 2048 x 16B segments (A 1024, B 1024); swizzled 128B rows
    auto load_stage = [&](int s, int k0) {
        const uint32_t st = base + s * STAGE_BYTES;
#pragma unroll
        for (int i = 0; i < 8; i++) {
            int seg = tid + i * 256;                 // 0..2047
            int r   = seg >> 3;                      // 0..255
            int c   = seg & 7;                       // 16B chunk
            bool isB = r >= 128;
            int rl  = r & 127;
            uint32_t dst = st + (isB ? TILE_BYTES : 0) + rl * 128 + ((c ^ (rl & 7)) * 16);
            int grow = (isB ? n0 : m0) + rl;
            cp16(dst, &g_F8[(size_t)grow * D + k0 + c * 16]);
        }
    };

    // f16 accumulators: [mi][n8 panel][2 regs of f16x2]
    uint32_t c[2][8][2];
#pragma unroll
    for (int mi = 0; mi < 2; mi++)
#pragma unroll
        for (int f = 0; f < 8; f++) { c[mi][f][0] = 0u; c[mi][f][1] = 0u; }

    load_stage(0, 0);
    asm volatile("cp.async.commit_group;" ::: "memory");
    load_stage(1, BKB);
    asm volatile("cp.async.commit_group;" ::: "memory");

    for (int ki = 0; ki < KITERS; ki++) {
        // sync first (stage being overwritten is no longer read), issue the
        // prefetch, THEN block on data for this iteration: wait_group 2 leaves
        // the two newest groups outstanding, guaranteeing stage ki has landed.
        __syncthreads();
        if (ki + 2 < KITERS) load_stage((ki + 2) % NSTAGE, (ki + 2) * BKB);
        asm volatile("cp.async.commit_group;" ::: "memory");
        asm volatile("cp.async.wait_group 2;" ::: "memory");

        const uint32_t sA = base + (ki % NSTAGE) * STAGE_BYTES;
        const uint32_t sB = sA + TILE_BYTES;
#pragma unroll
        for (int ks = 0; ks < 4; ks++) {             // four k32 slices per stage
            uint32_t a[2][4];
#pragma unroll
            for (int mi = 0; mi < 2; mi++) {
                int rA = wm * 32 + mi * 16 + (lane & 15);
                int chA = ks * 2 + (lane >> 4);
                ldmx4(a[mi], sA + rA * 128 + ((chA ^ (rA & 7)) * 16));
            }
#pragma unroll
            for (int nj = 0; nj < 4; nj++) {
                uint32_t b[4];
                int rB = wn * 64 + nj * 16 + (lane >> 4) * 8 + (lane & 7);
                int chB = ks * 2 + ((lane >> 3) & 1);
                ldmx4(b, sB + rB * 128 + ((chB ^ (rB & 7)) * 16));
#pragma unroll
                for (int mi = 0; mi < 2; mi++) {
                    mma_fp8h(c[mi][2 * nj],     a[mi], b[0], b[1]);
                    mma_fp8h(c[mi][2 * nj + 1], a[mi], b[2], b[3]);
                }
            }
        }
    }
    asm volatile("cp.async.wait_group 0;" ::: "memory");

    // ---------------- epilogue ----------------
    float cacc[16];
#pragma unroll
    for (int q = 0; q < 16; q++) cacc[q] = 0.0f;

#pragma unroll
    for (int mi = 0; mi < 2; mi++) {
        const int r_lo = m0 + wm * 32 + mi * 16 + (lane >> 2);
        const int r_hi = r_lo + 8;
        float rs0 = 0.0f, rs1 = 0.0f;
#pragma unroll
        for (int f = 0; f < 8; f++) {
            const int j0 = n0 + wn * 64 + f * 8 + (lane & 3) * 2;
            float2 lo = __half22float2(*(__half2*)&c[mi][f][0]);   // row r_lo
            float2 hi = __half22float2(*(__half2*)&c[mi][f][1]);   // row r_hi
            float e0 = ex2(lo.x * EXP2S);
            float e1 = ex2(lo.y * EXP2S);
            float e2 = ex2(hi.x * EXP2S);
            float e3 = ex2(hi.y * EXP2S);
            if (diag) {
                if (r_lo == j0)     e0 = 0.0f;
                if (r_lo == j0 + 1) e1 = 0.0f;
                if (r_hi == j0)     e2 = 0.0f;
                if (r_hi == j0 + 1) e3 = 0.0f;
            }
            rs0 += e0 + e1;
            rs1 += e2 + e3;
            cacc[2 * f]     += e0 + e2;
            cacc[2 * f + 1] += e1 + e3;
        }
        rs0 += __shfl_xor_sync(0xffffffffu, rs0, 1);
        rs0 += __shfl_xor_sync(0xffffffffu, rs0, 2);
        rs1 += __shfl_xor_sync(0xffffffffu, rs1, 1);
        rs1 += __shfl_xor_sync(0xffffffffu, rs1, 2);
        if ((lane & 3) == 0) {
            atomicAdd(&g_rowsum[r_lo], rs0);
            atomicAdd(&g_rowsum[r_hi], rs1);
        }
    }

    if (!diag) {
#pragma unroll
        for (int q = 0; q < 16; q++) {
            float v = cacc[q];
            v += __shfl_xor_sync(0xffffffffu, v, 4);
            v += __shfl_xor_sync(0xffffffffu, v, 8);
            v += __shfl_xor_sync(0xffffffffu, v, 16);
            cacc[q] = v;
        }
        if (lane < 4) {
#pragma unroll
            for (int f = 0; f < 8; f++) {
#pragma unroll
                for (int p = 0; p < 2; p++) {
                    int jl = wn * 64 + f * 8 + lane * 2 + p;
                    atomicAdd(&cs[jl], cacc[2 * f + p]);
                }
            }
        }
        __syncthreads();
        if (tid < 128) atomicAdd(&g_rowsum[n0 + tid], cs[tid]);
    }
}

extern "C" void kernel_launch(void* const* d_in, const int* in_sizes, int n_in,
                              void* d_out, int out_size) {
    const float* f1 = (const float*)d_in[0];
    const float* f2 = (const float*)d_in[1];
    float* out = (float*)d_out;

    cudaFuncSetAttribute(k_gemm, cudaFuncAttributeMaxDynamicSharedMemorySize, SMEM_DYN);

    k_prep<<<Bn / 8, 256>>>(f1, f2);
    k_gemm<<<NTRI, 256, SMEM_DYN>>>();
    k_final<<<1, 1024>>>(out);
}

// round 17
// speedup vs baseline: 1.0137x; 1.0137x over previous
#include <cuda_runtime.h>
#include <cuda_bf16.h>
#include <cuda_fp16.h>
#include <cuda_fp8.h>
#include <math.h>
#include <cstdint>

constexpr int Bn = 4096;
constexpr int D  = 1024;
constexpr int NR = 8192;
constexpr float INV_T = 1.0f / 0.07f;
constexpr float FP8_SCALE = 16.0f;                       // features stored as e4m3(16*f)
constexpr float EXP2S = 1.4426950408889634f / (0.07f * 256.0f);

constexpr int BM = 128, BN = 128;
constexpr int BKB = 128;                  // fp8 K elems per stage (full 128-B row)
constexpr int KITERS = D / BKB;           // 8
constexpr int NSTAGE = 3;
constexpr int TILE_BYTES  = 128 * 128;    // 16384
constexpr int STAGE_BYTES = 2 * TILE_BYTES;
constexpr int SMEM_DYN = NSTAGE * STAGE_BYTES + 512 + 16;
constexpr int NT = NR / BM;               // 64
constexpr int NTRI = NT * (NT + 1) / 2;   // 2080

__device__ uint8_t g_F8[(size_t)NR * D];
__device__ float g_rowsum[NR];
__device__ float g_posvec[Bn];

// ---------------- helpers ----------------
__device__ __forceinline__ uint32_t smem_u32(const void* p) {
    uint32_t a;
    asm("{ .reg .u64 t; cvta.to.shared.u64 t, %1; cvt.u32.u64 %0, t; }" : "=r"(a) : "l"(p));
    return a;
}
__device__ __forceinline__ void cp16(uint32_t dst, const void* src) {
    asm volatile("cp.async.cg.shared.global [%0], [%1], 16;" :: "r"(dst), "l"(src) : "memory");
}
__device__ __forceinline__ void ldmx4(uint32_t* r, uint32_t addr) {
    asm volatile("ldmatrix.sync.aligned.m8n8.x4.shared.b16 {%0,%1,%2,%3}, [%4];"
                 : "=r"(r[0]), "=r"(r[1]), "=r"(r[2]), "=r"(r[3]) : "r"(addr));
}
// fp8 mma with f16 accumulators
__device__ __forceinline__ void mma_fp8h(uint32_t* c, const uint32_t* a, uint32_t b0, uint32_t b1) {
    asm volatile("mma.sync.aligned.m16n8k32.row.col.f16.e4m3.e4m3.f16 "
                 "{%0,%1}, {%2,%3,%4,%5}, {%6,%7}, {%0,%1};"
                 : "+r"(c[0]), "+r"(c[1])
                 : "r"(a[0]), "r"(a[1]), "r"(a[2]), "r"(a[3]), "r"(b0), "r"(b1));
}
__device__ __forceinline__ float ex2(float x) {
    float r;
    asm("ex2.approx.ftz.f32 %0, %1;" : "=f"(r) : "f"(x));
    return r;
}
__device__ __forceinline__ float warpReduceSum(float v) {
#pragma unroll
    for (int o = 16; o > 0; o >>= 1) v += __shfl_xor_sync(0xffffffffu, v, o);
    return v;
}
__device__ __forceinline__ float blockReduceSum(float v) {
    __shared__ float sh[32];
    int lane = threadIdx.x & 31, wid = threadIdx.x >> 5;
    v = warpReduceSum(v);
    if (lane == 0) sh[wid] = v;
    __syncthreads();
    int nw = blockDim.x >> 5;
    v = (threadIdx.x < nw) ? sh[lane] : 0.0f;
    if (wid == 0) v = warpReduceSum(v);
    return v;
}

// ---------------- prep: warp per pair, genuine two-pass (low regs) ----------------
__global__ void __launch_bounds__(256) k_prep(const float* __restrict__ f1,
                                              const float* __restrict__ f2) {
    const int wid = threadIdx.x >> 5, lane = threadIdx.x & 31;
    const int i = blockIdx.x * 8 + wid;          // pair index
    const float* p1 = &f1[(size_t)i * D + lane * 4];
    const float* p2 = &f2[(size_t)i * D + lane * 4];

    // pass 1: streaming reduction, nothing held live
    float ss1 = 0.0f, ss2 = 0.0f, dd = 0.0f;
#pragma unroll
    for (int j = 0; j < 8; j++) {
        float4 a = *(const float4*)(p1 + j * 128);
        float4 b = *(const float4*)(p2 + j * 128);
        ss1 += a.x * a.x + a.y * a.y + a.z * a.z + a.w * a.w;
        ss2 += b.x * b.x + b.y * b.y + b.z * b.z + b.w * b.w;
        dd  += a.x * b.x + a.y * b.y + a.z * b.z + a.w * b.w;
    }
    ss1 = warpReduceSum(ss1);
    ss2 = warpReduceSum(ss2);
    dd  = warpReduceSum(dd);
    const float n1 = fmaxf(sqrtf(ss1), 1e-12f), n2 = fmaxf(sqrtf(ss2), 1e-12f);
    const float i1 = FP8_SCALE / n1, i2 = FP8_SCALE / n2;
    if (lane == 0) {
        g_posvec[i] = dd / (n1 * n2) * INV_T;
        g_rowsum[i] = 0.0f;
        g_rowsum[i + Bn] = 0.0f;
    }

    // compiler barrier: forbid CSE of pass-1 loads into pass 2 — forces
    // genuine reloads (L2-hot) so the 16 float4s aren't live across the
    // reductions. This is what drops regs ~87 -> ~40.
    asm volatile("" ::: "memory");

    // pass 2: reload + quantize
    uint8_t* q1 = &g_F8[(size_t)i * D + lane * 4];
    uint8_t* q2 = &g_F8[(size_t)(i + Bn) * D + lane * 4];
#pragma unroll
    for (int j = 0; j < 8; j++) {
        float4 a = *(const float4*)(p1 + j * 128);
        __nv_fp8_e4m3 a0(a.x * i1), a1(a.y * i1), a2(a.z * i1), a3(a.w * i1);
        *(uchar4*)(q1 + j * 128) =
            make_uchar4(*(uint8_t*)&a0, *(uint8_t*)&a1, *(uint8_t*)&a2, *(uint8_t*)&a3);
        float4 b = *(const float4*)(p2 + j * 128);
        __nv_fp8_e4m3 b0(b.x * i2), b1(b.y * i2), b2(b.z * i2), b3(b.w * i2);
        *(uchar4*)(q2 + j * 128) =
            make_uchar4(*(uint8_t*)&b0, *(uint8_t*)&b1, *(uint8_t*)&b2, *(uint8_t*)&b3);
    }
}

// ---------------- final reduction (separate kernel — keeps k_gemm regs low) ----------------
__global__ void k_final(float* __restrict__ out) {
    float4 v0 = *(const float4*)&g_rowsum[threadIdx.x * 8];
    float4 v1 = *(const float4*)&g_rowsum[threadIdx.x * 8 + 4];
    float s = __logf(v0.x) + __logf(v0.y) + __logf(v0.z) + __logf(v0.w)
            + __logf(v1.x) + __logf(v1.y) + __logf(v1.z) + __logf(v1.w);
    float4 p4 = *(const float4*)&g_posvec[threadIdx.x * 4];
    float p = p4.x + p4.y + p4.z + p4.w;
    s = blockReduceSum(s);
    __syncthreads();
    p = blockReduceSum(p);
    if (threadIdx.x == 0) out[0] = s / (float)NR - p / (float)Bn;
}

// ---------------- main GEMM (upper triangle) + exp/rowsum — round-15 config ----------------
__global__ void __launch_bounds__(256, 2) k_gemm() {
    const int t = blockIdx.x;
    int I = (int)(64.5f - sqrtf(64.5f * 64.5f - 2.0f * (float)t));
    while (NT * I - I * (I - 1) / 2 > t) I--;
    while (NT * (I + 1) - (I + 1) * I / 2 <= t) I++;
    const int J = I + (t - (NT * I - I * (I - 1) / 2));
    const bool diag = (I == J);
    const int m0 = I * BM, n0 = J * BN;

    extern __shared__ char smem_raw[];
    const uint32_t base = smem_u32(smem_raw);
    float* cs = (float*)(smem_raw + NSTAGE * STAGE_BYTES);

    const int tid = threadIdx.x, lane = tid & 31, wid = tid >> 5;
    const int wm = wid & 3, wn = wid >> 2;           // 4 x 2 warp grid, 32x64 warp tiles

    if (tid < 128) cs[tid] = 0.0f;

    // stage loader: 2048 x 16B segments (A 1024, B 1024); swizzled 128B rows
    auto load_stage = [&](int s, int k0) {
        const uint32_t st = base + s * STAGE_BYTES;
#pragma unroll
        for (int i = 0; i < 8; i++) {
            int seg = tid + i * 256;                 // 0..2047
            int r   = seg >> 3;                      // 0..255
            int c   = seg & 7;                       // 16B chunk
            bool isB = r >= 128;
            int rl  = r & 127;
            uint32_t dst = st + (isB ? TILE_BYTES : 0) + rl * 128 + ((c ^ (rl & 7)) * 16);
            int grow = (isB ? n0 : m0) + rl;
            cp16(dst, &g_F8[(size_t)grow * D + k0 + c * 16]);
        }
    };

    // f16 accumulators: [mi][n8 panel][2 regs of f16x2]
    uint32_t c[2][8][2];
#pragma unroll
    for (int mi = 0; mi < 2; mi++)
#pragma unroll
        for (int f = 0; f < 8; f++) { c[mi][f][0] = 0u; c[mi][f][1] = 0u; }

    load_stage(0, 0);
    asm volatile("cp.async.commit_group;" ::: "memory");
    load_stage(1, BKB);
    asm volatile("cp.async.commit_group;" ::: "memory");

    for (int ki = 0; ki < KITERS; ki++) {
        asm volatile("cp.async.wait_group 1;" ::: "memory");
        __syncthreads();
        if (ki + 2 < KITERS) load_stage((ki + 2) % NSTAGE, (ki + 2) * BKB);
        asm volatile("cp.async.commit_group;" ::: "memory");

        const uint32_t sA = base + (ki % NSTAGE) * STAGE_BYTES;
        const uint32_t sB = sA + TILE_BYTES;
#pragma unroll
        for (int ks = 0; ks < 4; ks++) {             // four k32 slices per stage
            uint32_t a[2][4];
#pragma unroll
            for (int mi = 0; mi < 2; mi++) {
                int rA = wm * 32 + mi * 16 + (lane & 15);
                int chA = ks * 2 + (lane >> 4);
                ldmx4(a[mi], sA + rA * 128 + ((chA ^ (rA & 7)) * 16));
            }
#pragma unroll
            for (int nj = 0; nj < 4; nj++) {
                uint32_t b[4];
                int rB = wn * 64 + nj * 16 + (lane >> 4) * 8 + (lane & 7);
                int chB = ks * 2 + ((lane >> 3) & 1);
                ldmx4(b, sB + rB * 128 + ((chB ^ (rB & 7)) * 16));
#pragma unroll
                for (int mi = 0; mi < 2; mi++) {
                    mma_fp8h(c[mi][2 * nj],     a[mi], b[0], b[1]);
                    mma_fp8h(c[mi][2 * nj + 1], a[mi], b[2], b[3]);
                }
            }
        }
    }
    asm volatile("cp.async.wait_group 0;" ::: "memory");

    // ---------------- epilogue ----------------
    float cacc[16];
#pragma unroll
    for (int q = 0; q < 16; q++) cacc[q] = 0.0f;

#pragma unroll
    for (int mi = 0; mi < 2; mi++) {
        const int r_lo = m0 + wm * 32 + mi * 16 + (lane >> 2);
        const int r_hi = r_lo + 8;
        float rs0 = 0.0f, rs1 = 0.0f;
#pragma unroll
        for (int f = 0; f < 8; f++) {
            const int j0 = n0 + wn * 64 + f * 8 + (lane & 3) * 2;
            float2 lo = __half22float2(*(__half2*)&c[mi][f][0]);   // row r_lo
            float2 hi = __half22float2(*(__half2*)&c[mi][f][1]);   // row r_hi
            float e0 = ex2(lo.x * EXP2S);
            float e1 = ex2(lo.y * EXP2S);
            float e2 = ex2(hi.x * EXP2S);
            float e3 = ex2(hi.y * EXP2S);
            if (diag) {
                if (r_lo == j0)     e0 = 0.0f;
                if (r_lo == j0 + 1) e1 = 0.0f;
                if (r_hi == j0)     e2 = 0.0f;
                if (r_hi == j0 + 1) e3 = 0.0f;
            }
            rs0 += e0 + e1;
            rs1 += e2 + e3;
            cacc[2 * f]     += e0 + e2;
            cacc[2 * f + 1] += e1 + e3;
        }
        rs0 += __shfl_xor_sync(0xffffffffu, rs0, 1);
        rs0 += __shfl_xor_sync(0xffffffffu, rs0, 2);
        rs1 += __shfl_xor_sync(0xffffffffu, rs1, 1);
        rs1 += __shfl_xor_sync(0xffffffffu, rs1, 2);
        if ((lane & 3) == 0) {
            atomicAdd(&g_rowsum[r_lo], rs0);
            atomicAdd(&g_rowsum[r_hi], rs1);
        }
    }

    if (!diag) {
#pragma unroll
        for (int q = 0; q < 16; q++) {
            float v = cacc[q];
            v += __shfl_xor_sync(0xffffffffu, v, 4);
            v += __shfl_xor_sync(0xffffffffu, v, 8);
            v += __shfl_xor_sync(0xffffffffu, v, 16);
            cacc[q] = v;
        }
        if (lane < 4) {
#pragma unroll
            for (int f = 0; f < 8; f++) {
#pragma unroll
                for (int p = 0; p < 2; p++) {
                    int jl = wn * 64 + f * 8 + lane * 2 + p;
                    atomicAdd(&cs[jl], cacc[2 * f + p]);
                }
            }
        }
        __syncthreads();
        if (tid < 128) atomicAdd(&g_rowsum[n0 + tid], cs[tid]);
    }
}

extern "C" void kernel_launch(void* const* d_in, const int* in_sizes, int n_in,
                              void* d_out, int out_size) {
    const float* f1 = (const float*)d_in[0];
    const float* f2 = (const float*)d_in[1];
    float* out = (float*)d_out;

    cudaFuncSetAttribute(k_gemm, cudaFuncAttributeMaxDynamicSharedMemorySize, SMEM_DYN);

    k_prep<<<Bn / 8, 256>>>(f1, f2);
    k_gemm<<<NTRI, 256, SMEM_DYN>>>();
    k_final<<<1, 1024>>>(out);
}